// round 16
// baseline (speedup 1.0000x reference)
#include <cuda_runtime.h>

// LengthRegulator: out[b,t,:] = x[b, tok(b,t), :] where tok = searchsorted(cumsum(dur), t, 'right')
// Static shapes: B=16, L=512, D=512, T_MAX=4096. Output fp32 [B, T, D].
//
// Single-wave persistent fused kernel:
//  grid = (37, 16) = 592 blocks = exactly 4 blocks/SM on 148 SMs (one wave, no tail).
//  Each block is pinned to batch blockIdx.y, scans that batch's durations ONCE,
//  then loops over its 3-4 assigned 32-frame chunks (2 frames per warp,
//  fully-coalesced warp-strided float4 gather, streaming stores).

constexpr int B = 16;
constexpr int L = 512;
constexpr int D = 512;          // 512 floats = 128 float4 per row
constexpr int T = 4096;
constexpr int D4 = D / 4;       // 128 float4 per row
constexpr int FPB = 32;         // frames per chunk
constexpr int CHUNKS = T / FPB;             // 128 chunks per batch
constexpr int JBLK = 37;                    // blocks per batch (16*37 = 592 = 4*148)

__global__ void __launch_bounds__(512) fused_kernel(
    const int*    __restrict__ dur,
    const float4* __restrict__ x4,
    float4*       __restrict__ out4)
{
    __shared__ int s[L];          // inclusive cumsum of durations for this batch
    __shared__ int wsum[16];      // per-warp scan totals

    const int tid  = threadIdx.x;        // 0..511
    const int lane = tid & 31;
    const int wrp  = tid >> 5;           // 0..15
    const int b    = blockIdx.y;         // batch
    const int j    = blockIdx.x;         // 0..36

    // ---- one scan of dur[b, 0..511] per block ----
    int v = dur[b * L + tid];
    #pragma unroll
    for (int off = 1; off < 32; off <<= 1) {
        int n = __shfl_up_sync(0xffffffffu, v, off);
        if (lane >= off) v += n;
    }
    if (lane == 31) wsum[wrp] = v;
    __syncthreads();

    if (wrp == 0 && lane < 16) {
        int p = wsum[lane];
        #pragma unroll
        for (int off = 1; off < 16; off <<= 1) {
            int n = __shfl_up_sync(0x0000ffffu, p, off);
            if (lane >= off) p += n;
        }
        wsum[lane] = p;
    }
    __syncthreads();

    const int base = (wrp > 0) ? wsum[wrp - 1] : 0;
    s[tid] = v + base;
    __syncthreads();

    const int total = s[L - 1];

    // ---- chunk range for this block: 17 blocks get 4 chunks, 20 get 3 (sum=128) ----
    const int c0  = j * 3 + (j < 17 ? j : 17);
    const int cnt = 3 + (j < 17 ? 1 : 0);

    const float4* xb = x4 + (b * L) * D4 + lane;

    for (int c = 0; c < cnt; ++c) {
        const int chunk = c0 + c;
        const int fr0   = b * T + chunk * FPB + wrp * 2;   // warp's first frame
        const int fr    = fr0 + (lane >> 4);               // half-warp split
        const int t     = fr & (T - 1);

        // parallel half-warp upper_bound searches (SMEM, broadcast-friendly)
        int tok;
        if (t >= total) {
            tok = -1;
        } else {
            int lo = 0, hi = L;
            while (lo < hi) {
                int mid = (lo + hi) >> 1;
                if (s[mid] <= t) lo = mid + 1; else hi = mid;
            }
            tok = lo < (L - 1) ? lo : (L - 1);
        }
        const int tok0 = __shfl_sync(0xffffffffu, tok, 0);
        const int tok1 = __shfl_sync(0xffffffffu, tok, 16);

        float4* dst0 = out4 + fr0 * D4 + lane;
        float4* dst1 = dst0 + D4;

        if (tok0 >= 0 && tok1 >= 0) {
            const float4* s0 = xb + tok0 * D4;
            const float4* s1 = xb + tok1 * D4;
            float4 a0 = __ldg(s0 +  0);
            float4 a1 = __ldg(s0 + 32);
            float4 a2 = __ldg(s0 + 64);
            float4 a3 = __ldg(s0 + 96);
            float4 q0 = __ldg(s1 +  0);
            float4 q1 = __ldg(s1 + 32);
            float4 q2 = __ldg(s1 + 64);
            float4 q3 = __ldg(s1 + 96);
            __stcs(dst0 +  0, a0);
            __stcs(dst0 + 32, a1);
            __stcs(dst0 + 64, a2);
            __stcs(dst0 + 96, a3);
            __stcs(dst1 +  0, q0);
            __stcs(dst1 + 32, q1);
            __stcs(dst1 + 64, q2);
            __stcs(dst1 + 96, q3);
        } else {
            const float4 z = make_float4(0.f, 0.f, 0.f, 0.f);
            if (tok0 >= 0) {
                const float4* s0 = xb + tok0 * D4;
                float4 a0 = __ldg(s0 +  0);
                float4 a1 = __ldg(s0 + 32);
                float4 a2 = __ldg(s0 + 64);
                float4 a3 = __ldg(s0 + 96);
                __stcs(dst0 +  0, a0);
                __stcs(dst0 + 32, a1);
                __stcs(dst0 + 64, a2);
                __stcs(dst0 + 96, a3);
            } else {
                __stcs(dst0 +  0, z);
                __stcs(dst0 + 32, z);
                __stcs(dst0 + 64, z);
                __stcs(dst0 + 96, z);
            }
            if (tok1 >= 0) {
                const float4* s1 = xb + tok1 * D4;
                float4 q0 = __ldg(s1 +  0);
                float4 q1 = __ldg(s1 + 32);
                float4 q2 = __ldg(s1 + 64);
                float4 q3 = __ldg(s1 + 96);
                __stcs(dst1 +  0, q0);
                __stcs(dst1 + 32, q1);
                __stcs(dst1 + 64, q2);
                __stcs(dst1 + 96, q3);
            } else {
                __stcs(dst1 +  0, z);
                __stcs(dst1 + 32, z);
                __stcs(dst1 + 64, z);
                __stcs(dst1 + 96, z);
            }
        }
    }
}

extern "C" void kernel_launch(void* const* d_in, const int* in_sizes, int n_in,
                              void* d_out, int out_size) {
    const float* x   = (const float*)d_in[0];
    const int*   dur = (const int*)d_in[1];
    // d_in[2] = mel_max_length (static 4096, baked into constants)

    dim3 grid(JBLK, B);                 // 592 blocks = one full wave at 4 blocks/SM
    fused_kernel<<<grid, 512>>>(dur, (const float4*)x, (float4*)d_out);

    (void)in_sizes; (void)n_in; (void)out_size;
}